// round 1
// baseline (speedup 1.0000x reference)
#include <cuda_runtime.h>
#include <cuda_bf16.h>
#include <mma.h>

using namespace nvcuda;

// Problem constants
#define BB 8192
#define DD 1024
#define EE 8
#define HH 4096
#define KK 2

#define RROWS (BB * KK)            // 16384 routed rows
#define RPAD  17408                // 16384 + 8*128 worst-case padding
#define MTILES (RPAD / 128)        // 136 fixed M-tiles

// GEMM tiling
#define BM 128
#define BN 128
#define BK 32
#define ASTRIDE 36
#define BSTRIDE 136
#define NWARPS 8
#define NTHREADS 256

// -------- device scratch (static: allocation rules forbid cudaMalloc) --------
__device__ int   g_tok_e[RROWS];
__device__ float g_tok_w[RROWS];
__device__ int   g_counts[EE];
__device__ int   g_cursor[EE];
__device__ int   g_poff[EE + 1];
__device__ int   g_row_token[RPAD];
__device__ float g_row_w[RPAD];
__device__ int   g_tile_expert[MTILES];
__device__ float g_h[(size_t)RPAD * HH];   // 285 MB fp32 activations

typedef wmma::fragment<wmma::matrix_a, 16, 16, 8, wmma::precision::tf32, wmma::row_major> FragA;
typedef wmma::fragment<wmma::matrix_b, 16, 16, 8, wmma::precision::tf32, wmma::row_major> FragB;
typedef wmma::fragment<wmma::accumulator, 16, 16, 8, float> FragC;

// ---------------------------------------------------------------------------
// init: zero out, counts, cursors; fill row_token with -1
// ---------------------------------------------------------------------------
__global__ void init_kernel(float* out) {
    int idx = blockIdx.x * blockDim.x + threadIdx.x;   // 8192*1024 threads
    out[idx] = 0.0f;
    if (idx < RPAD) { g_row_token[idx] = -1; g_row_w[idx] = 0.0f; }
    if (idx < EE)   { g_counts[idx] = 0; g_cursor[idx] = 0; }
}

// ---------------------------------------------------------------------------
// gate: logits = z @ Wg + bg, softmax, top-2
// 1 warp per token, 8 warps / block, grid = 1024
// ---------------------------------------------------------------------------
__global__ __launch_bounds__(256) void gate_kernel(const float* __restrict__ z,
                                                   const float* __restrict__ Wg,
                                                   const float* __restrict__ bg) {
    __shared__ float sWgT[EE * DD];   // transposed: [e][d], conflict-free LDS
    int tid = threadIdx.x;
    for (int i = tid; i < DD * EE; i += 256) {
        int d = i >> 3, e = i & 7;
        sWgT[e * DD + d] = Wg[i];
    }
    __syncthreads();

    int warp = tid >> 5, lane = tid & 31;
    int t = blockIdx.x * 8 + warp;
    const float* zrow = z + (size_t)t * DD;

    float acc[EE];
#pragma unroll
    for (int e = 0; e < EE; e++) acc[e] = 0.0f;

    for (int d = lane; d < DD; d += 32) {
        float zv = zrow[d];
#pragma unroll
        for (int e = 0; e < EE; e++) acc[e] += zv * sWgT[e * DD + d];
    }
#pragma unroll
    for (int e = 0; e < EE; e++) {
#pragma unroll
        for (int off = 16; off; off >>= 1)
            acc[e] += __shfl_xor_sync(0xffffffffu, acc[e], off);
    }

    if (lane == 0) {
        float l[EE];
        float m = -1e30f;
#pragma unroll
        for (int e = 0; e < EE; e++) { l[e] = acc[e] + bg[e]; m = fmaxf(m, l[e]); }
        float p[EE], Z = 0.0f;
#pragma unroll
        for (int e = 0; e < EE; e++) { p[e] = expf(l[e] - m); Z += p[e]; }
        // top-2 (ties -> lower index, matching top_k)
        float b1v = -1.0f, b2v = -1.0f; int i1 = 0, i2 = 0;
#pragma unroll
        for (int e = 0; e < EE; e++) {
            if (p[e] > b1v)      { b2v = b1v; i2 = i1; b1v = p[e]; i1 = e; }
            else if (p[e] > b2v) { b2v = p[e]; i2 = e; }
        }
        float invZ = 1.0f / Z;
        g_tok_e[t * 2 + 0] = i1;  g_tok_w[t * 2 + 0] = b1v * invZ;
        g_tok_e[t * 2 + 1] = i2;  g_tok_w[t * 2 + 1] = b2v * invZ;
        atomicAdd(&g_counts[i1], 1);
        atomicAdd(&g_counts[i2], 1);
    }
}

// ---------------------------------------------------------------------------
// offsets: padded segment offsets + per-tile expert ids (single block)
// ---------------------------------------------------------------------------
__global__ void offsets_kernel() {
    __shared__ int s_poff[EE + 1];
    int tid = threadIdx.x;
    if (tid == 0) {
        int acc = 0;
        for (int e = 0; e < EE; e++) {
            s_poff[e] = acc;
            acc += ((g_counts[e] + 127) >> 7) << 7;
        }
        s_poff[EE] = acc;
        for (int e = 0; e <= EE; e++) g_poff[e] = s_poff[e];
    }
    __syncthreads();
    if (tid < MTILES) {
        int r = tid << 7;
        int ex = 0;
        for (int e = 0; e < EE; e++)
            if (r >= s_poff[e] && r < s_poff[e + 1]) ex = e;
        g_tile_expert[tid] = ex;
    }
}

// ---------------------------------------------------------------------------
// scatter: build permuted row lists (order within expert is arbitrary; final
// combine is 2 commutative fp adds per output -> deterministic result)
// ---------------------------------------------------------------------------
__global__ void scatter_kernel() {
    int idx = blockIdx.x * blockDim.x + threadIdx.x;
    if (idx >= RROWS) return;
    int e = g_tok_e[idx];
    int pos = g_poff[e] + atomicAdd(&g_cursor[e], 1);
    g_row_token[pos] = idx >> 1;
    g_row_w[pos] = g_tok_w[idx];
}

// ---------------------------------------------------------------------------
// GEMM1: h = relu(gather(z) @ W1[e] + b1[e]),  [128 x 4096-tile x K=1024]
// ---------------------------------------------------------------------------
__global__ __launch_bounds__(NTHREADS) void gemm1_kernel(const float* __restrict__ z,
                                                         const float* __restrict__ W1,
                                                         const float* __restrict__ b1) {
    __shared__ __align__(16) float sA[BM * ASTRIDE];
    __shared__ __align__(16) float sB[BK * BSTRIDE];
    __shared__ int sTok[BM];

    const int mt = blockIdx.y;
    const int n0 = blockIdx.x * BN;
    const int e = g_tile_expert[mt];
    const int row0 = mt * BM;
    const int tid = threadIdx.x;

    if (tid < BM) sTok[tid] = g_row_token[row0 + tid];
    __syncthreads();

    const float* Be = W1 + (size_t)e * DD * HH;   // [D][H] row-major

    const int warp = tid >> 5, lane = tid & 31;
    (void)lane;
    const int wm = warp & 3;        // 0..3 -> 32-row bands
    const int wn = warp >> 2;       // 0..1 -> 64-col bands

    FragC acc[2][4];
#pragma unroll
    for (int i = 0; i < 2; i++)
#pragma unroll
        for (int j = 0; j < 4; j++) wmma::fill_fragment(acc[i][j], 0.0f);

    for (int k0 = 0; k0 < DD; k0 += BK) {
        // A: gather 128x32
#pragma unroll
        for (int rep = 0; rep < 4; rep++) {
            int idx = rep * 256 + tid;
            int m = idx >> 3, q = idx & 7;
            int tok = sTok[m];
            float4 v = make_float4(0.f, 0.f, 0.f, 0.f);
            if (tok >= 0) v = *(const float4*)(z + (size_t)tok * DD + k0 + q * 4);
            *(float4*)(sA + m * ASTRIDE + q * 4) = v;
        }
        // B: 32x128 contiguous
#pragma unroll
        for (int rep = 0; rep < 4; rep++) {
            int idx = rep * 256 + tid;
            int r = idx >> 5, c4 = idx & 31;
            float4 v = *(const float4*)(Be + (size_t)(k0 + r) * HH + n0 + c4 * 4);
            *(float4*)(sB + r * BSTRIDE + c4 * 4) = v;
        }
        __syncthreads();

#pragma unroll
        for (int ks = 0; ks < BK / 8; ks++) {
            FragA a[2]; FragB b[4];
#pragma unroll
            for (int i = 0; i < 2; i++) {
                wmma::load_matrix_sync(a[i], sA + (wm * 32 + i * 16) * ASTRIDE + ks * 8, ASTRIDE);
#pragma unroll
                for (int t = 0; t < a[i].num_elements; t++)
                    a[i].x[t] = wmma::__float_to_tf32(a[i].x[t]);
            }
#pragma unroll
            for (int j = 0; j < 4; j++) {
                wmma::load_matrix_sync(b[j], sB + (ks * 8) * BSTRIDE + wn * 64 + j * 16, BSTRIDE);
#pragma unroll
                for (int t = 0; t < b[j].num_elements; t++)
                    b[j].x[t] = wmma::__float_to_tf32(b[j].x[t]);
            }
#pragma unroll
            for (int i = 0; i < 2; i++)
#pragma unroll
                for (int j = 0; j < 4; j++)
                    wmma::mma_sync(acc[i][j], a[i], b[j], acc[i][j]);
        }
        __syncthreads();
    }

    // epilogue: +b1, relu, store to g_h  (bias as replicated fragment)
    for (int idx = tid; idx < 16 * BN; idx += 256) {
        int r = idx >> 7, c = idx & 127;
        sB[r * BSTRIDE + c] = b1[(size_t)e * HH + n0 + c];
    }
    __syncthreads();

    FragC biasf[4];
#pragma unroll
    for (int j = 0; j < 4; j++)
        wmma::load_matrix_sync(biasf[j], sB + wn * 64 + j * 16, BSTRIDE, wmma::mem_row_major);

#pragma unroll
    for (int i = 0; i < 2; i++)
#pragma unroll
        for (int j = 0; j < 4; j++) {
#pragma unroll
            for (int t = 0; t < acc[i][j].num_elements; t++)
                acc[i][j].x[t] = fmaxf(acc[i][j].x[t] + biasf[j].x[t], 0.0f);
            wmma::store_matrix_sync(
                g_h + (size_t)(row0 + wm * 32 + i * 16) * HH + n0 + wn * 64 + j * 16,
                acc[i][j], HH, wmma::mem_row_major);
        }
}

// ---------------------------------------------------------------------------
// GEMM2: y = h @ W2[e] + b2[e]; out[token] += w * y  (atomic scatter)
// ---------------------------------------------------------------------------
__global__ __launch_bounds__(NTHREADS) void gemm2_kernel(const float* __restrict__ W2,
                                                         const float* __restrict__ b2,
                                                         float* __restrict__ out) {
    __shared__ __align__(16) float sA[BM * ASTRIDE];
    __shared__ __align__(16) float sB[BK * BSTRIDE];
    __shared__ int   sTok[BM];
    __shared__ float sRowW[BM];
    __shared__ float sB2[BN];

    const int mt = blockIdx.y;
    const int n0 = blockIdx.x * BN;
    const int e = g_tile_expert[mt];
    const int row0 = mt * BM;
    const int tid = threadIdx.x;

    if (tid < BM) {
        sTok[tid] = g_row_token[row0 + tid];
        sRowW[tid] = g_row_w[row0 + tid];
        sB2[tid] = b2[(size_t)e * DD + n0 + tid];
    }
    __syncthreads();

    const float* Be = W2 + (size_t)e * HH * DD;   // [H][D] row-major

    const int warp = tid >> 5, lane = tid & 31;
    const int wm = warp & 3;
    const int wn = warp >> 2;

    FragC acc[2][4];
#pragma unroll
    for (int i = 0; i < 2; i++)
#pragma unroll
        for (int j = 0; j < 4; j++) wmma::fill_fragment(acc[i][j], 0.0f);

    for (int k0 = 0; k0 < HH; k0 += BK) {
        // A: contiguous rows of g_h
#pragma unroll
        for (int rep = 0; rep < 4; rep++) {
            int idx = rep * 256 + tid;
            int m = idx >> 3, q = idx & 7;
            float4 v = *(const float4*)(g_h + (size_t)(row0 + m) * HH + k0 + q * 4);
            *(float4*)(sA + m * ASTRIDE + q * 4) = v;
        }
        // B: 32x128
#pragma unroll
        for (int rep = 0; rep < 4; rep++) {
            int idx = rep * 256 + tid;
            int r = idx >> 5, c4 = idx & 31;
            float4 v = *(const float4*)(Be + (size_t)(k0 + r) * DD + n0 + c4 * 4);
            *(float4*)(sB + r * BSTRIDE + c4 * 4) = v;
        }
        __syncthreads();

#pragma unroll
        for (int ks = 0; ks < BK / 8; ks++) {
            FragA a[2]; FragB b[4];
#pragma unroll
            for (int i = 0; i < 2; i++) {
                wmma::load_matrix_sync(a[i], sA + (wm * 32 + i * 16) * ASTRIDE + ks * 8, ASTRIDE);
#pragma unroll
                for (int t = 0; t < a[i].num_elements; t++)
                    a[i].x[t] = wmma::__float_to_tf32(a[i].x[t]);
            }
#pragma unroll
            for (int j = 0; j < 4; j++) {
                wmma::load_matrix_sync(b[j], sB + (ks * 8) * BSTRIDE + wn * 64 + j * 16, BSTRIDE);
#pragma unroll
                for (int t = 0; t < b[j].num_elements; t++)
                    b[j].x[t] = wmma::__float_to_tf32(b[j].x[t]);
            }
#pragma unroll
            for (int i = 0; i < 2; i++)
#pragma unroll
                for (int j = 0; j < 4; j++)
                    wmma::mma_sync(acc[i][j], a[i], b[j], acc[i][j]);
        }
        __syncthreads();
    }

    // epilogue: stage each 16x16 frag to per-warp smem, then +b2, *w, atomicAdd
    float* buf = sA + warp * (16 * 20);   // 20-float ld (80B, 16B-aligned)
#pragma unroll
    for (int i = 0; i < 2; i++)
#pragma unroll
        for (int j = 0; j < 4; j++) {
            wmma::store_matrix_sync(buf, acc[i][j], 20, wmma::mem_row_major);
            __syncwarp();
            for (int idx = lane; idx < 256; idx += 32) {
                int r = idx >> 4, c = idx & 15;
                int ml = wm * 32 + i * 16 + r;
                int tok = sTok[ml];
                if (tok >= 0) {
                    float val = buf[r * 20 + c] + sB2[wn * 64 + j * 16 + c];
                    atomicAdd(out + (size_t)tok * DD + n0 + wn * 64 + j * 16 + c,
                              sRowW[ml] * val);
                }
            }
            __syncwarp();
        }
}

// ---------------------------------------------------------------------------
extern "C" void kernel_launch(void* const* d_in, const int* in_sizes, int n_in,
                              void* d_out, int out_size) {
    const float* z  = (const float*)d_in[0];
    const float* Wg = (const float*)d_in[1];
    const float* bg = (const float*)d_in[2];
    const float* W1 = (const float*)d_in[3];
    const float* b1 = (const float*)d_in[4];
    const float* W2 = (const float*)d_in[5];
    const float* b2 = (const float*)d_in[6];
    float* out = (float*)d_out;

    init_kernel<<<BB * DD / 1024, 1024>>>(out);
    gate_kernel<<<BB / 8, 256>>>(z, Wg, bg);
    offsets_kernel<<<1, 256>>>();
    scatter_kernel<<<RROWS / 256, 256>>>();
    gemm1_kernel<<<dim3(HH / BN, MTILES), NTHREADS>>>(z, W1, b1);
    gemm2_kernel<<<dim3(DD / BN, MTILES), NTHREADS>>>(W2, b2, out);
}

// round 2
// speedup vs baseline: 1.0065x; 1.0065x over previous
#include <cuda_runtime.h>
#include <cuda_bf16.h>
#include <mma.h>

using namespace nvcuda;

// Problem constants
#define BB 8192
#define DD 1024
#define EE 8
#define HH 4096
#define KK 2

#define RROWS (BB * KK)            // 16384 routed rows
#define RPAD  17408                // 16384 + 8*128 worst-case padding
#define MTILES (RPAD / 128)        // 136 fixed M-tiles

// GEMM tiling
#define BM 128
#define BN 128
#define BK 32
#define ASTRIDE 36
#define BSTRIDE 136
#define NWARPS 8
#define NTHREADS 256

// -------- device scratch (static: allocation rules forbid cudaMalloc) --------
__device__ int   g_tok_e[RROWS];
__device__ float g_tok_w[RROWS];
__device__ int   g_counts[EE];
__device__ int   g_cursor[EE];
__device__ int   g_poff[EE + 1];
__device__ int   g_row_token[RPAD];
__device__ float g_row_w[RPAD];
__device__ int   g_tile_expert[MTILES];
__device__ float g_h[(size_t)RPAD * HH];   // 285 MB fp32 activations

typedef wmma::fragment<wmma::matrix_a, 16, 16, 8, wmma::precision::tf32, wmma::row_major> FragA;
typedef wmma::fragment<wmma::matrix_b, 16, 16, 8, wmma::precision::tf32, wmma::row_major> FragB;
typedef wmma::fragment<wmma::accumulator, 16, 16, 8, float> FragC;

// ---------------------------------------------------------------------------
// init: zero out, counts, cursors; fill row_token with -1
// ---------------------------------------------------------------------------
__global__ void init_kernel(float* out) {
    int idx = blockIdx.x * blockDim.x + threadIdx.x;   // 8192*1024 threads
    out[idx] = 0.0f;
    if (idx < RPAD) { g_row_token[idx] = -1; g_row_w[idx] = 0.0f; }
    if (idx < EE)   { g_counts[idx] = 0; g_cursor[idx] = 0; }
}

// ---------------------------------------------------------------------------
// gate: logits = z @ Wg + bg, softmax, top-2
// 1 warp per token, 8 warps / block, grid = 1024
// ---------------------------------------------------------------------------
__global__ __launch_bounds__(256) void gate_kernel(const float* __restrict__ z,
                                                   const float* __restrict__ Wg,
                                                   const float* __restrict__ bg) {
    __shared__ float sWgT[EE * DD];   // transposed: [e][d], conflict-free LDS
    int tid = threadIdx.x;
    for (int i = tid; i < DD * EE; i += 256) {
        int d = i >> 3, e = i & 7;
        sWgT[e * DD + d] = Wg[i];
    }
    __syncthreads();

    int warp = tid >> 5, lane = tid & 31;
    int t = blockIdx.x * 8 + warp;
    const float* zrow = z + (size_t)t * DD;

    float acc[EE];
#pragma unroll
    for (int e = 0; e < EE; e++) acc[e] = 0.0f;

    for (int d = lane; d < DD; d += 32) {
        float zv = zrow[d];
#pragma unroll
        for (int e = 0; e < EE; e++) acc[e] += zv * sWgT[e * DD + d];
    }
#pragma unroll
    for (int e = 0; e < EE; e++) {
#pragma unroll
        for (int off = 16; off; off >>= 1)
            acc[e] += __shfl_xor_sync(0xffffffffu, acc[e], off);
    }

    if (lane == 0) {
        float l[EE];
        float m = -1e30f;
#pragma unroll
        for (int e = 0; e < EE; e++) { l[e] = acc[e] + bg[e]; m = fmaxf(m, l[e]); }
        float p[EE], Z = 0.0f;
#pragma unroll
        for (int e = 0; e < EE; e++) { p[e] = expf(l[e] - m); Z += p[e]; }
        // top-2 (ties -> lower index, matching top_k)
        float b1v = -1.0f, b2v = -1.0f; int i1 = 0, i2 = 0;
#pragma unroll
        for (int e = 0; e < EE; e++) {
            if (p[e] > b1v)      { b2v = b1v; i2 = i1; b1v = p[e]; i1 = e; }
            else if (p[e] > b2v) { b2v = p[e]; i2 = e; }
        }
        float invZ = 1.0f / Z;
        g_tok_e[t * 2 + 0] = i1;  g_tok_w[t * 2 + 0] = b1v * invZ;
        g_tok_e[t * 2 + 1] = i2;  g_tok_w[t * 2 + 1] = b2v * invZ;
        atomicAdd(&g_counts[i1], 1);
        atomicAdd(&g_counts[i2], 1);
    }
}

// ---------------------------------------------------------------------------
// offsets: padded segment offsets + per-tile expert ids (single block)
// ---------------------------------------------------------------------------
__global__ void offsets_kernel() {
    __shared__ int s_poff[EE + 1];
    int tid = threadIdx.x;
    if (tid == 0) {
        int acc = 0;
        for (int e = 0; e < EE; e++) {
            s_poff[e] = acc;
            acc += ((g_counts[e] + 127) >> 7) << 7;
        }
        s_poff[EE] = acc;
        for (int e = 0; e <= EE; e++) g_poff[e] = s_poff[e];
    }
    __syncthreads();
    if (tid < MTILES) {
        int r = tid << 7;
        int ex = 0;
        for (int e = 0; e < EE; e++)
            if (r >= s_poff[e] && r < s_poff[e + 1]) ex = e;
        g_tile_expert[tid] = ex;
    }
}

// ---------------------------------------------------------------------------
// scatter: build permuted row lists (order within expert is arbitrary; final
// combine is 2 commutative fp adds per output -> deterministic result)
// ---------------------------------------------------------------------------
__global__ void scatter_kernel() {
    int idx = blockIdx.x * blockDim.x + threadIdx.x;
    if (idx >= RROWS) return;
    int e = g_tok_e[idx];
    int pos = g_poff[e] + atomicAdd(&g_cursor[e], 1);
    g_row_token[pos] = idx >> 1;
    g_row_w[pos] = g_tok_w[idx];
}

// ---------------------------------------------------------------------------
// GEMM1: h = relu(gather(z) @ W1[e] + b1[e]),  [128 x 4096-tile x K=1024]
// ---------------------------------------------------------------------------
__global__ __launch_bounds__(NTHREADS) void gemm1_kernel(const float* __restrict__ z,
                                                         const float* __restrict__ W1,
                                                         const float* __restrict__ b1) {
    __shared__ __align__(16) float sA[BM * ASTRIDE];
    __shared__ __align__(16) float sB[BK * BSTRIDE];
    __shared__ int sTok[BM];

    const int mt = blockIdx.y;
    const int n0 = blockIdx.x * BN;
    const int e = g_tile_expert[mt];
    const int row0 = mt * BM;
    const int tid = threadIdx.x;

    if (tid < BM) sTok[tid] = g_row_token[row0 + tid];
    __syncthreads();

    const float* Be = W1 + (size_t)e * DD * HH;   // [D][H] row-major

    const int warp = tid >> 5, lane = tid & 31;
    (void)lane;
    const int wm = warp & 3;        // 0..3 -> 32-row bands
    const int wn = warp >> 2;       // 0..1 -> 64-col bands

    FragC acc[2][4];
#pragma unroll
    for (int i = 0; i < 2; i++)
#pragma unroll
        for (int j = 0; j < 4; j++) wmma::fill_fragment(acc[i][j], 0.0f);

    for (int k0 = 0; k0 < DD; k0 += BK) {
        // A: gather 128x32
#pragma unroll
        for (int rep = 0; rep < 4; rep++) {
            int idx = rep * 256 + tid;
            int m = idx >> 3, q = idx & 7;
            int tok = sTok[m];
            float4 v = make_float4(0.f, 0.f, 0.f, 0.f);
            if (tok >= 0) v = *(const float4*)(z + (size_t)tok * DD + k0 + q * 4);
            *(float4*)(sA + m * ASTRIDE + q * 4) = v;
        }
        // B: 32x128 contiguous
#pragma unroll
        for (int rep = 0; rep < 4; rep++) {
            int idx = rep * 256 + tid;
            int r = idx >> 5, c4 = idx & 31;
            float4 v = *(const float4*)(Be + (size_t)(k0 + r) * HH + n0 + c4 * 4);
            *(float4*)(sB + r * BSTRIDE + c4 * 4) = v;
        }
        __syncthreads();

#pragma unroll
        for (int ks = 0; ks < BK / 8; ks++) {
            FragA a[2]; FragB b[4];
#pragma unroll
            for (int i = 0; i < 2; i++) {
                wmma::load_matrix_sync(a[i], sA + (wm * 32 + i * 16) * ASTRIDE + ks * 8, ASTRIDE);
#pragma unroll
                for (int t = 0; t < a[i].num_elements; t++)
                    a[i].x[t] = wmma::__float_to_tf32(a[i].x[t]);
            }
#pragma unroll
            for (int j = 0; j < 4; j++) {
                wmma::load_matrix_sync(b[j], sB + (ks * 8) * BSTRIDE + wn * 64 + j * 16, BSTRIDE);
#pragma unroll
                for (int t = 0; t < b[j].num_elements; t++)
                    b[j].x[t] = wmma::__float_to_tf32(b[j].x[t]);
            }
#pragma unroll
            for (int i = 0; i < 2; i++)
#pragma unroll
                for (int j = 0; j < 4; j++)
                    wmma::mma_sync(acc[i][j], a[i], b[j], acc[i][j]);
        }
        __syncthreads();
    }

    // epilogue: +b1, relu, store to g_h  (bias as replicated fragment)
    for (int idx = tid; idx < 16 * BN; idx += 256) {
        int r = idx >> 7, c = idx & 127;
        sB[r * BSTRIDE + c] = b1[(size_t)e * HH + n0 + c];
    }
    __syncthreads();

    FragC biasf[4];
#pragma unroll
    for (int j = 0; j < 4; j++)
        wmma::load_matrix_sync(biasf[j], sB + wn * 64 + j * 16, BSTRIDE, wmma::mem_row_major);

#pragma unroll
    for (int i = 0; i < 2; i++)
#pragma unroll
        for (int j = 0; j < 4; j++) {
#pragma unroll
            for (int t = 0; t < acc[i][j].num_elements; t++)
                acc[i][j].x[t] = fmaxf(acc[i][j].x[t] + biasf[j].x[t], 0.0f);
            wmma::store_matrix_sync(
                g_h + (size_t)(row0 + wm * 32 + i * 16) * HH + n0 + wn * 64 + j * 16,
                acc[i][j], HH, wmma::mem_row_major);
        }
}

// ---------------------------------------------------------------------------
// GEMM2: y = h @ W2[e] + b2[e]; out[token] += w * y  (atomic scatter)
// ---------------------------------------------------------------------------
__global__ __launch_bounds__(NTHREADS) void gemm2_kernel(const float* __restrict__ W2,
                                                         const float* __restrict__ b2,
                                                         float* __restrict__ out) {
    __shared__ __align__(16) float sA[BM * ASTRIDE];
    __shared__ __align__(16) float sB[BK * BSTRIDE];
    __shared__ int   sTok[BM];
    __shared__ float sRowW[BM];
    __shared__ float sB2[BN];

    const int mt = blockIdx.y;
    const int n0 = blockIdx.x * BN;
    const int e = g_tile_expert[mt];
    const int row0 = mt * BM;
    const int tid = threadIdx.x;

    if (tid < BM) {
        sTok[tid] = g_row_token[row0 + tid];
        sRowW[tid] = g_row_w[row0 + tid];
        sB2[tid] = b2[(size_t)e * DD + n0 + tid];
    }
    __syncthreads();

    const float* Be = W2 + (size_t)e * HH * DD;   // [H][D] row-major

    const int warp = tid >> 5, lane = tid & 31;
    const int wm = warp & 3;
    const int wn = warp >> 2;

    FragC acc[2][4];
#pragma unroll
    for (int i = 0; i < 2; i++)
#pragma unroll
        for (int j = 0; j < 4; j++) wmma::fill_fragment(acc[i][j], 0.0f);

    for (int k0 = 0; k0 < HH; k0 += BK) {
        // A: contiguous rows of g_h
#pragma unroll
        for (int rep = 0; rep < 4; rep++) {
            int idx = rep * 256 + tid;
            int m = idx >> 3, q = idx & 7;
            float4 v = *(const float4*)(g_h + (size_t)(row0 + m) * HH + k0 + q * 4);
            *(float4*)(sA + m * ASTRIDE + q * 4) = v;
        }
        // B: 32x128
#pragma unroll
        for (int rep = 0; rep < 4; rep++) {
            int idx = rep * 256 + tid;
            int r = idx >> 5, c4 = idx & 31;
            float4 v = *(const float4*)(Be + (size_t)(k0 + r) * DD + n0 + c4 * 4);
            *(float4*)(sB + r * BSTRIDE + c4 * 4) = v;
        }
        __syncthreads();

#pragma unroll
        for (int ks = 0; ks < BK / 8; ks++) {
            FragA a[2]; FragB b[4];
#pragma unroll
            for (int i = 0; i < 2; i++) {
                wmma::load_matrix_sync(a[i], sA + (wm * 32 + i * 16) * ASTRIDE + ks * 8, ASTRIDE);
#pragma unroll
                for (int t = 0; t < a[i].num_elements; t++)
                    a[i].x[t] = wmma::__float_to_tf32(a[i].x[t]);
            }
#pragma unroll
            for (int j = 0; j < 4; j++) {
                wmma::load_matrix_sync(b[j], sB + (ks * 8) * BSTRIDE + wn * 64 + j * 16, BSTRIDE);
#pragma unroll
                for (int t = 0; t < b[j].num_elements; t++)
                    b[j].x[t] = wmma::__float_to_tf32(b[j].x[t]);
            }
#pragma unroll
            for (int i = 0; i < 2; i++)
#pragma unroll
                for (int j = 0; j < 4; j++)
                    wmma::mma_sync(acc[i][j], a[i], b[j], acc[i][j]);
        }
        __syncthreads();
    }

    // epilogue: stage each 16x16 frag to per-warp smem, then +b2, *w, atomicAdd
    float* buf = sA + warp * (16 * 20);   // 20-float ld (80B, 16B-aligned)
#pragma unroll
    for (int i = 0; i < 2; i++)
#pragma unroll
        for (int j = 0; j < 4; j++) {
            wmma::store_matrix_sync(buf, acc[i][j], 20, wmma::mem_row_major);
            __syncwarp();
            for (int idx = lane; idx < 256; idx += 32) {
                int r = idx >> 4, c = idx & 15;
                int ml = wm * 32 + i * 16 + r;
                int tok = sTok[ml];
                if (tok >= 0) {
                    float val = buf[r * 20 + c] + sB2[wn * 64 + j * 16 + c];
                    atomicAdd(out + (size_t)tok * DD + n0 + wn * 64 + j * 16 + c,
                              sRowW[ml] * val);
                }
            }
            __syncwarp();
        }
}

// ---------------------------------------------------------------------------
extern "C" void kernel_launch(void* const* d_in, const int* in_sizes, int n_in,
                              void* d_out, int out_size) {
    const float* z  = (const float*)d_in[0];
    const float* Wg = (const float*)d_in[1];
    const float* bg = (const float*)d_in[2];
    const float* W1 = (const float*)d_in[3];
    const float* b1 = (const float*)d_in[4];
    const float* W2 = (const float*)d_in[5];
    const float* b2 = (const float*)d_in[6];
    float* out = (float*)d_out;

    init_kernel<<<BB * DD / 1024, 1024>>>(out);
    gate_kernel<<<BB / 8, 256>>>(z, Wg, bg);
    offsets_kernel<<<1, 256>>>();
    scatter_kernel<<<RROWS / 256, 256>>>();
    gemm1_kernel<<<dim3(HH / BN, MTILES), NTHREADS>>>(z, W1, b1);
    gemm2_kernel<<<dim3(DD / BN, MTILES), NTHREADS>>>(W2, b2, out);
}

// round 6
// speedup vs baseline: 1.5936x; 1.5833x over previous
#include <cuda_runtime.h>
#include <cstdint>
#include <mma.h>

using namespace nvcuda;

#define BB 8192
#define DD 1024
#define EE 8
#define HH 4096
#define RROWS (BB * 2)
#define RPAD  17408              // 16384 + 8*128 pad
#define MTILES 136               // RPAD / 128

#define BM 128
#define BN 128
#define BK 16
#define ASTR 20                  // A stride (floats): 128 rows x 16 + pad
#define BSTR 136                 // B stride (floats): 16 rows x 128 + pad
#define ASZ (BM * ASTR)          // 2560 floats
#define BSZ (BK * BSTR)          // 2176 floats
#define STG (ASZ + BSZ)          // 4736 floats per stage

// ---------------- device scratch ----------------
__device__ int   g_tok_e[RROWS];
__device__ float g_tok_w[RROWS];
__device__ int   g_tok_pos[RROWS];
__device__ int   g_counts[EE];
__device__ int   g_cursor[EE];
__device__ int   g_poff[EE + 1];
__device__ int   g_row_token[RPAD];
__device__ int   g_tile_expert[MTILES];
__device__ float g_h[(size_t)RPAD * HH];
__device__ float g_y[(size_t)RPAD * DD];

typedef wmma::fragment<wmma::matrix_a, 16, 16, 8, wmma::precision::tf32, wmma::row_major> FragA;
typedef wmma::fragment<wmma::matrix_b, 16, 16, 8, wmma::precision::tf32, wmma::row_major> FragB;
typedef wmma::fragment<wmma::accumulator, 16, 16, 8, float> FragC;

__device__ __forceinline__ uint32_t smem_u32(const void* p) {
    uint32_t a;
    asm("{ .reg .u64 t; cvta.to.shared.u64 t, %1; cvt.u32.u64 %0, t; }" : "=r"(a) : "l"(p));
    return a;
}
__device__ __forceinline__ void cpa16(uint32_t dst, const void* src, uint32_t sz) {
    asm volatile("cp.async.cg.shared.global [%0], [%1], 16, %2;" :: "r"(dst), "l"(src), "r"(sz));
}
#define CPA_COMMIT() asm volatile("cp.async.commit_group;")
#define CPA_WAIT1()  asm volatile("cp.async.wait_group 1;")
#define CPA_WAIT0()  asm volatile("cp.async.wait_group 0;")

// ---------------------------------------------------------------------------
__global__ void init_kernel() {
    int idx = blockIdx.x * blockDim.x + threadIdx.x;
    if (idx < RPAD) g_row_token[idx] = -1;
    if (idx < EE)   { g_counts[idx] = 0; g_cursor[idx] = 0; }
}

// ---------------------------------------------------------------------------
__global__ __launch_bounds__(256) void gate_kernel(const float* __restrict__ z,
                                                   const float* __restrict__ Wg,
                                                   const float* __restrict__ bg) {
    __shared__ float sWgT[EE * DD];
    int tid = threadIdx.x;
    for (int i = tid; i < DD * EE; i += 256) {
        int d = i >> 3, e = i & 7;
        sWgT[e * DD + d] = Wg[i];
    }
    __syncthreads();
    int warp = tid >> 5, lane = tid & 31;
    int t = blockIdx.x * 8 + warp;
    const float* zrow = z + (size_t)t * DD;
    float acc[EE];
#pragma unroll
    for (int e = 0; e < EE; e++) acc[e] = 0.0f;
    for (int d = lane; d < DD; d += 32) {
        float zv = zrow[d];
#pragma unroll
        for (int e = 0; e < EE; e++) acc[e] += zv * sWgT[e * DD + d];
    }
#pragma unroll
    for (int e = 0; e < EE; e++)
#pragma unroll
        for (int off = 16; off; off >>= 1)
            acc[e] += __shfl_xor_sync(0xffffffffu, acc[e], off);
    if (lane == 0) {
        float l[EE], m = -1e30f;
#pragma unroll
        for (int e = 0; e < EE; e++) { l[e] = acc[e] + bg[e]; m = fmaxf(m, l[e]); }
        float p[EE], Z = 0.0f;
#pragma unroll
        for (int e = 0; e < EE; e++) { p[e] = expf(l[e] - m); Z += p[e]; }
        float b1v = -1.0f, b2v = -1.0f; int i1 = 0, i2 = 0;
#pragma unroll
        for (int e = 0; e < EE; e++) {
            if (p[e] > b1v)      { b2v = b1v; i2 = i1; b1v = p[e]; i1 = e; }
            else if (p[e] > b2v) { b2v = p[e]; i2 = e; }
        }
        float invZ = 1.0f / Z;
        g_tok_e[t * 2 + 0] = i1;  g_tok_w[t * 2 + 0] = b1v * invZ;
        g_tok_e[t * 2 + 1] = i2;  g_tok_w[t * 2 + 1] = b2v * invZ;
        atomicAdd(&g_counts[i1], 1);
        atomicAdd(&g_counts[i2], 1);
    }
}

__global__ void offsets_kernel() {
    __shared__ int s_poff[EE + 1];
    int tid = threadIdx.x;
    if (tid == 0) {
        int acc = 0;
        for (int e = 0; e < EE; e++) {
            s_poff[e] = acc;
            acc += ((g_counts[e] + 127) >> 7) << 7;
        }
        s_poff[EE] = acc;
        for (int e = 0; e <= EE; e++) g_poff[e] = s_poff[e];
    }
    __syncthreads();
    if (tid < MTILES) {
        int r = tid << 7;
        int ex = 0;
        for (int e = 0; e < EE; e++)
            if (r >= s_poff[e] && r < s_poff[e + 1]) ex = e;
        g_tile_expert[tid] = ex;
    }
}

__global__ void scatter_kernel() {
    int idx = blockIdx.x * blockDim.x + threadIdx.x;
    if (idx >= RROWS) return;
    int e = g_tok_e[idx];
    int pos = g_poff[e] + atomicAdd(&g_cursor[e], 1);
    g_row_token[pos] = idx >> 1;
    g_tok_pos[idx] = pos;
}

// ---------------------------------------------------------------------------
// Grouped GEMM, R1-proven core (128x128 tile, 8 warps 4x2 of 32x64, in-frag
// tf32 conversion) + 2-stage cp.async pipeline (BK=16), static smem only.
// WHICH=1: h = relu(gather(z) @ W1[e] + b1) -> g_h
// WHICH=2: y = g_h @ W2[e] + b2             -> g_y
// ---------------------------------------------------------------------------
template <int WHICH>
__global__ __launch_bounds__(256) void moe_gemm(const float* __restrict__ z,
                                                const float* __restrict__ W_glb,
                                                const float* __restrict__ bias) {
    __shared__ __align__(16) float smem[2 * STG];
    __shared__ int stok[BM];

    const int KDIM = (WHICH == 1) ? DD : HH;
    const int NOUT = (WHICH == 1) ? HH : DD;
    const int NK = KDIM / BK;
    const int bx = blockIdx.x;
    const int n0 = blockIdx.y * BN;
    const int e = g_tile_expert[bx];
    const int row0 = bx * BM;
    const int tid = threadIdx.x, warp = tid >> 5;
    const int wm = warp & 3, wn = warp >> 2;      // R1 layout: 4x2 warps, 32x64 each

    const float* Wr = W_glb + (size_t)e * KDIM * NOUT;

    if (tid < BM) stok[tid] = (WHICH == 1) ? g_row_token[row0 + tid] : 0;
    __syncthreads();

    const uint32_t sbase = smem_u32(smem);

    // stage fill: 512 A chunks (128 rows x 4) + 512 B chunks (16 rows x 32)
    auto fill = [&](int kf, int s) {
        uint32_t sa = sbase + s * STG * 4;
        uint32_t sb = sa + ASZ * 4;
        int k0 = kf * BK;
#pragma unroll
        for (int rep = 0; rep < 4; rep++) {
            int i = rep * 256 + tid;
            if (i < 512) {
                int row = i >> 2, q = i & 3;
                uint32_t dst = sa + (row * ASTR + q * 4) * 4;
                if (WHICH == 1) {
                    int tok = stok[row];
                    const float* src = (tok < 0) ? z
                        : z + (size_t)tok * DD + k0 + q * 4;
                    cpa16(dst, src, tok < 0 ? 0u : 16u);
                } else {
                    cpa16(dst, g_h + (size_t)(row0 + row) * HH + k0 + q * 4, 16u);
                }
            } else {
                int j = i - 512;
                int r = j >> 5, c = j & 31;
                uint32_t dst = sb + (r * BSTR + c * 4) * 4;
                cpa16(dst, Wr + (size_t)(k0 + r) * NOUT + n0 + c * 4, 16u);
            }
        }
    };

    FragC acc[2][4];
#pragma unroll
    for (int i = 0; i < 2; i++)
#pragma unroll
        for (int j = 0; j < 4; j++) wmma::fill_fragment(acc[i][j], 0.0f);

    fill(0, 0);
    CPA_COMMIT();                                 // G0

    for (int kt = 0; kt < NK; kt++) {
        if (kt + 1 < NK) fill(kt + 1, (kt + 1) & 1);
        CPA_COMMIT();                             // G_{kt+1}
        CPA_WAIT1();                              // G0..G_kt complete
        __syncthreads();
        const float* sA = smem + (kt & 1) * STG;
        const float* sB = sA + ASZ;
#pragma unroll
        for (int ks = 0; ks < BK / 8; ks++) {
            FragA a[2]; FragB b[4];
#pragma unroll
            for (int i = 0; i < 2; i++) {
                wmma::load_matrix_sync(a[i], sA + (wm * 32 + i * 16) * ASTR + ks * 8, ASTR);
#pragma unroll
                for (int t = 0; t < a[i].num_elements; t++)
                    a[i].x[t] = wmma::__float_to_tf32(a[i].x[t]);
            }
#pragma unroll
            for (int j = 0; j < 4; j++) {
                wmma::load_matrix_sync(b[j], sB + (ks * 8) * BSTR + wn * 64 + j * 16, BSTR);
#pragma unroll
                for (int t = 0; t < b[j].num_elements; t++)
                    b[j].x[t] = wmma::__float_to_tf32(b[j].x[t]);
            }
#pragma unroll
            for (int i = 0; i < 2; i++)
#pragma unroll
                for (int j = 0; j < 4; j++)
                    wmma::mma_sync(acc[i][j], a[i], b[j], acc[i][j]);
        }
        __syncthreads();
    }

    // ---- epilogue: bias (+relu for GEMM1), direct store, no atomics ----
    CPA_WAIT0();
    __syncthreads();
    for (int i = tid; i < 16 * BN; i += 256) {
        int r = i >> 7, c = i & 127;
        smem[r * BSTR + c] = bias[(size_t)e * NOUT + n0 + c];
    }
    __syncthreads();

    FragC biasf[4];
#pragma unroll
    for (int j = 0; j < 4; j++)
        wmma::load_matrix_sync(biasf[j], smem + wn * 64 + j * 16, BSTR, wmma::mem_row_major);

    float* gdst = (WHICH == 1) ? g_h : g_y;
#pragma unroll
    for (int i = 0; i < 2; i++)
#pragma unroll
        for (int j = 0; j < 4; j++) {
#pragma unroll
            for (int t = 0; t < acc[i][j].num_elements; t++) {
                float v = acc[i][j].x[t] + biasf[j].x[t];
                if (WHICH == 1) v = fmaxf(v, 0.0f);
                acc[i][j].x[t] = v;
            }
            wmma::store_matrix_sync(
                gdst + (size_t)(row0 + wm * 32 + i * 16) * NOUT + n0 + wn * 64 + j * 16,
                acc[i][j], NOUT, wmma::mem_row_major);
        }
}

// out[t] = w0 * y[p0] + w1 * y[p1]
__global__ void combine_kernel(float* __restrict__ out) {
    int idx = blockIdx.x * blockDim.x + threadIdx.x;   // BB*256 float4 units
    int t = idx >> 8, j = idx & 255;
    int p0 = g_tok_pos[2 * t], p1 = g_tok_pos[2 * t + 1];
    float w0 = g_tok_w[2 * t], w1 = g_tok_w[2 * t + 1];
    float4 a = ((const float4*)(g_y + (size_t)p0 * DD))[j];
    float4 b = ((const float4*)(g_y + (size_t)p1 * DD))[j];
    float4 o;
    o.x = w0 * a.x + w1 * b.x;
    o.y = w0 * a.y + w1 * b.y;
    o.z = w0 * a.z + w1 * b.z;
    o.w = w0 * a.w + w1 * b.w;
    ((float4*)out)[idx] = o;
}

// ---------------------------------------------------------------------------
extern "C" void kernel_launch(void* const* d_in, const int* in_sizes, int n_in,
                              void* d_out, int out_size) {
    const float* z  = (const float*)d_in[0];
    const float* Wg = (const float*)d_in[1];
    const float* bg = (const float*)d_in[2];
    const float* W1 = (const float*)d_in[3];
    const float* b1 = (const float*)d_in[4];
    const float* W2 = (const float*)d_in[5];
    const float* b2 = (const float*)d_in[6];
    float* out = (float*)d_out;

    init_kernel<<<(RPAD + 255) / 256, 256>>>();
    gate_kernel<<<BB / 8, 256>>>(z, Wg, bg);
    offsets_kernel<<<1, 256>>>();
    scatter_kernel<<<RROWS / 256, 256>>>();
    moe_gemm<1><<<dim3(MTILES, HH / BN), 256>>>(z, W1, b1);
    moe_gemm<2><<<dim3(MTILES, DD / BN), 256>>>(z, W2, b2);
    combine_kernel<<<BB, 256>>>(out);
}

// round 7
// speedup vs baseline: 1.7434x; 1.0940x over previous
#include <cuda_runtime.h>
#include <cstdint>
#include <mma.h>

using namespace nvcuda;

#define BB 8192
#define DD 1024
#define EE 8
#define HH 4096
#define RROWS (BB * 2)
#define RPAD  17408              // 16384 + 8*128 pad
#define MTILES 136               // RPAD / 128

#define BM 128
#define BN 256
#define BK 32
#define ASTR 36                  // A stride: 32 + 4 pad
#define BSTR 264                 // B stride: 256 + 8 pad
#define ASZ (BM * ASTR)          // 4608 floats
#define BSZ (BK * BSTR)          // 8448 floats
#define STG (ASZ + BSZ)          // 13056 floats / stage
#define SMEMSZ (2 * STG * 4)     // 104448 bytes

// ---------------- device scratch ----------------
__device__ int   g_tok_e[RROWS];
__device__ float g_tok_w[RROWS];
__device__ int   g_tok_pos[RROWS];
__device__ int   g_counts[EE];
__device__ int   g_cursor[EE];
__device__ int   g_poff[EE + 1];
__device__ int   g_row_token[RPAD];
__device__ int   g_tile_expert[MTILES];
__device__ float g_h[(size_t)RPAD * HH];
__device__ float g_y[(size_t)RPAD * DD];

typedef wmma::fragment<wmma::matrix_a, 16, 16, 8, wmma::precision::tf32, wmma::row_major> FragA;
typedef wmma::fragment<wmma::matrix_b, 16, 16, 8, wmma::precision::tf32, wmma::row_major> FragB;
typedef wmma::fragment<wmma::accumulator, 16, 16, 8, float> FragC;

__device__ __forceinline__ uint32_t smem_u32(const void* p) {
    uint32_t a;
    asm("{ .reg .u64 t; cvta.to.shared.u64 t, %1; cvt.u32.u64 %0, t; }" : "=r"(a) : "l"(p));
    return a;
}
__device__ __forceinline__ void cpa16(uint32_t dst, const void* src, uint32_t sz) {
    asm volatile("cp.async.cg.shared.global [%0], [%1], 16, %2;" :: "r"(dst), "l"(src), "r"(sz));
}
#define CPA_COMMIT() asm volatile("cp.async.commit_group;")
#define CPA_WAIT1()  asm volatile("cp.async.wait_group 1;")
#define CPA_WAIT0()  asm volatile("cp.async.wait_group 0;")

// ---------------------------------------------------------------------------
__global__ void init_kernel() {
    int idx = blockIdx.x * blockDim.x + threadIdx.x;
    if (idx < RPAD) g_row_token[idx] = -1;
    if (idx < EE)   { g_counts[idx] = 0; g_cursor[idx] = 0; }
}

// ---------------------------------------------------------------------------
__global__ __launch_bounds__(256) void gate_kernel(const float* __restrict__ z,
                                                   const float* __restrict__ Wg,
                                                   const float* __restrict__ bg) {
    __shared__ float sWgT[EE * DD];
    int tid = threadIdx.x;
    for (int i = tid; i < DD * EE; i += 256) {
        int d = i >> 3, e = i & 7;
        sWgT[e * DD + d] = Wg[i];
    }
    __syncthreads();
    int warp = tid >> 5, lane = tid & 31;
    int t = blockIdx.x * 8 + warp;
    const float* zrow = z + (size_t)t * DD;
    float acc[EE];
#pragma unroll
    for (int e = 0; e < EE; e++) acc[e] = 0.0f;
    for (int d = lane; d < DD; d += 32) {
        float zv = zrow[d];
#pragma unroll
        for (int e = 0; e < EE; e++) acc[e] += zv * sWgT[e * DD + d];
    }
#pragma unroll
    for (int e = 0; e < EE; e++)
#pragma unroll
        for (int off = 16; off; off >>= 1)
            acc[e] += __shfl_xor_sync(0xffffffffu, acc[e], off);
    if (lane == 0) {
        float l[EE], m = -1e30f;
#pragma unroll
        for (int e = 0; e < EE; e++) { l[e] = acc[e] + bg[e]; m = fmaxf(m, l[e]); }
        float p[EE], Z = 0.0f;
#pragma unroll
        for (int e = 0; e < EE; e++) { p[e] = expf(l[e] - m); Z += p[e]; }
        float b1v = -1.0f, b2v = -1.0f; int i1 = 0, i2 = 0;
#pragma unroll
        for (int e = 0; e < EE; e++) {
            if (p[e] > b1v)      { b2v = b1v; i2 = i1; b1v = p[e]; i1 = e; }
            else if (p[e] > b2v) { b2v = p[e]; i2 = e; }
        }
        float invZ = 1.0f / Z;
        g_tok_e[t * 2 + 0] = i1;  g_tok_w[t * 2 + 0] = b1v * invZ;
        g_tok_e[t * 2 + 1] = i2;  g_tok_w[t * 2 + 1] = b2v * invZ;
        atomicAdd(&g_counts[i1], 1);
        atomicAdd(&g_counts[i2], 1);
    }
}

__global__ void offsets_kernel() {
    __shared__ int s_poff[EE + 1];
    int tid = threadIdx.x;
    if (tid == 0) {
        int acc = 0;
        for (int e = 0; e < EE; e++) {
            s_poff[e] = acc;
            acc += ((g_counts[e] + 127) >> 7) << 7;
        }
        s_poff[EE] = acc;
        for (int e = 0; e <= EE; e++) g_poff[e] = s_poff[e];
    }
    __syncthreads();
    if (tid < MTILES) {
        int r = tid << 7;
        int ex = 0;
        for (int e = 0; e < EE; e++)
            if (r >= s_poff[e] && r < s_poff[e + 1]) ex = e;
        g_tile_expert[tid] = ex;
    }
}

__global__ void scatter_kernel() {
    int idx = blockIdx.x * blockDim.x + threadIdx.x;
    if (idx >= RROWS) return;
    int e = g_tok_e[idx];
    int pos = g_poff[e] + atomicAdd(&g_cursor[e], 1);
    g_row_token[pos] = idx >> 1;
    g_tok_pos[idx] = pos;
}

// ---------------------------------------------------------------------------
// Grouped GEMM: R6-proven pipeline skeleton, tile grown to 128x256, BK=32.
// 8 warps (2 x 4), each 64 x 64 (acc[4][4]). Dynamic smem, 2 stages.
// WHICH=1: h = relu(gather(z) @ W1[e] + b1) -> g_h
// WHICH=2: y = g_h @ W2[e] + b2             -> g_y
// ---------------------------------------------------------------------------
template <int WHICH>
__global__ __launch_bounds__(256) void moe_gemm(const float* __restrict__ z,
                                                const float* __restrict__ W_glb,
                                                const float* __restrict__ bias) {
    extern __shared__ __align__(16) float smem[];
    __shared__ int stok[BM];

    const int KDIM = (WHICH == 1) ? DD : HH;
    const int NOUT = (WHICH == 1) ? HH : DD;
    const int NK = KDIM / BK;
    const int bx = blockIdx.x;
    const int n0 = blockIdx.y * BN;
    const int e = g_tile_expert[bx];
    const int row0 = bx * BM;
    const int tid = threadIdx.x, warp = tid >> 5;
    const int wm = warp >> 2, wn = warp & 3;      // 2 x 4 warps, 64 x 64 each

    const float* Wr = W_glb + (size_t)e * KDIM * NOUT;

    if (tid < BM) stok[tid] = (WHICH == 1) ? g_row_token[row0 + tid] : 0;
    __syncthreads();

    const uint32_t sbase = smem_u32(smem);

    // stage fill: A = 1024 chunks (128 rows x 8), B = 2048 chunks (32 rows x 64)
    auto fill = [&](int kf, int s) {
        uint32_t sa = sbase + s * STG * 4;
        uint32_t sb = sa + ASZ * 4;
        int k0 = kf * BK;
#pragma unroll
        for (int rep = 0; rep < 12; rep++) {
            int i = rep * 256 + tid;
            if (i < 1024) {
                int row = i >> 3, q = i & 7;
                uint32_t dst = sa + (row * ASTR + q * 4) * 4;
                if (WHICH == 1) {
                    int tok = stok[row];
                    const float* src = (tok < 0) ? z
                        : z + (size_t)tok * DD + k0 + q * 4;
                    cpa16(dst, src, tok < 0 ? 0u : 16u);
                } else {
                    cpa16(dst, g_h + (size_t)(row0 + row) * HH + k0 + q * 4, 16u);
                }
            } else {
                int j = i - 1024;
                int r = j >> 6, c = j & 63;
                uint32_t dst = sb + (r * BSTR + c * 4) * 4;
                cpa16(dst, Wr + (size_t)(k0 + r) * NOUT + n0 + c * 4, 16u);
            }
        }
    };

    FragC acc[4][4];
#pragma unroll
    for (int i = 0; i < 4; i++)
#pragma unroll
        for (int j = 0; j < 4; j++) wmma::fill_fragment(acc[i][j], 0.0f);

    fill(0, 0);
    CPA_COMMIT();                                 // G0

    for (int kt = 0; kt < NK; kt++) {
        if (kt + 1 < NK) fill(kt + 1, (kt + 1) & 1);
        CPA_COMMIT();                             // G_{kt+1}
        CPA_WAIT1();                              // G0..G_kt complete
        __syncthreads();
        const float* sA = smem + (kt & 1) * STG;
        const float* sB = sA + ASZ;
#pragma unroll
        for (int ks = 0; ks < BK / 8; ks++) {
            FragA a[4]; FragB b[4];
#pragma unroll
            for (int i = 0; i < 4; i++) {
                wmma::load_matrix_sync(a[i], sA + (wm * 64 + i * 16) * ASTR + ks * 8, ASTR);
#pragma unroll
                for (int t = 0; t < a[i].num_elements; t++)
                    a[i].x[t] = wmma::__float_to_tf32(a[i].x[t]);
            }
#pragma unroll
            for (int j = 0; j < 4; j++) {
                wmma::load_matrix_sync(b[j], sB + (ks * 8) * BSTR + wn * 64 + j * 16, BSTR);
#pragma unroll
                for (int t = 0; t < b[j].num_elements; t++)
                    b[j].x[t] = wmma::__float_to_tf32(b[j].x[t]);
            }
#pragma unroll
            for (int i = 0; i < 4; i++)
#pragma unroll
                for (int j = 0; j < 4; j++)
                    wmma::mma_sync(acc[i][j], a[i], b[j], acc[i][j]);
        }
        __syncthreads();
    }

    // ---- epilogue: bias (+relu for GEMM1), direct store, no atomics ----
    CPA_WAIT0();
    __syncthreads();
    for (int i = tid; i < 16 * BN; i += 256) {
        int r = i >> 8, c = i & 255;
        smem[r * BSTR + c] = bias[(size_t)e * NOUT + n0 + c];
    }
    __syncthreads();

    FragC biasf[4];
#pragma unroll
    for (int j = 0; j < 4; j++)
        wmma::load_matrix_sync(biasf[j], smem + wn * 64 + j * 16, BSTR, wmma::mem_row_major);

    float* gdst = (WHICH == 1) ? g_h : g_y;
#pragma unroll
    for (int i = 0; i < 4; i++)
#pragma unroll
        for (int j = 0; j < 4; j++) {
#pragma unroll
            for (int t = 0; t < acc[i][j].num_elements; t++) {
                float v = acc[i][j].x[t] + biasf[j].x[t];
                if (WHICH == 1) v = fmaxf(v, 0.0f);
                acc[i][j].x[t] = v;
            }
            wmma::store_matrix_sync(
                gdst + (size_t)(row0 + wm * 64 + i * 16) * NOUT + n0 + wn * 64 + j * 16,
                acc[i][j], NOUT, wmma::mem_row_major);
        }
}

// out[t] = w0 * y[p0] + w1 * y[p1]
__global__ void combine_kernel(float* __restrict__ out) {
    int idx = blockIdx.x * blockDim.x + threadIdx.x;   // BB*256 float4 units
    int t = idx >> 8, j = idx & 255;
    int p0 = g_tok_pos[2 * t], p1 = g_tok_pos[2 * t + 1];
    float w0 = g_tok_w[2 * t], w1 = g_tok_w[2 * t + 1];
    float4 a = ((const float4*)(g_y + (size_t)p0 * DD))[j];
    float4 b = ((const float4*)(g_y + (size_t)p1 * DD))[j];
    float4 o;
    o.x = w0 * a.x + w1 * b.x;
    o.y = w0 * a.y + w1 * b.y;
    o.z = w0 * a.z + w1 * b.z;
    o.w = w0 * a.w + w1 * b.w;
    ((float4*)out)[idx] = o;
}

// ---------------------------------------------------------------------------
extern "C" void kernel_launch(void* const* d_in, const int* in_sizes, int n_in,
                              void* d_out, int out_size) {
    const float* z  = (const float*)d_in[0];
    const float* Wg = (const float*)d_in[1];
    const float* bg = (const float*)d_in[2];
    const float* W1 = (const float*)d_in[3];
    const float* b1 = (const float*)d_in[4];
    const float* W2 = (const float*)d_in[5];
    const float* b2 = (const float*)d_in[6];
    float* out = (float*)d_out;

    cudaFuncSetAttribute(moe_gemm<1>, cudaFuncAttributeMaxDynamicSharedMemorySize, SMEMSZ);
    cudaFuncSetAttribute(moe_gemm<2>, cudaFuncAttributeMaxDynamicSharedMemorySize, SMEMSZ);

    init_kernel<<<(RPAD + 255) / 256, 256>>>();
    gate_kernel<<<BB / 8, 256>>>(z, Wg, bg);
    offsets_kernel<<<1, 256>>>();
    scatter_kernel<<<RROWS / 256, 256>>>();
    moe_gemm<1><<<dim3(MTILES, HH / BN), 256, SMEMSZ>>>(z, W1, b1);
    moe_gemm<2><<<dim3(MTILES, DD / BN), 256, SMEMSZ>>>(z, W2, b2);
    combine_kernel<<<BB, 256>>>(out);
}